// round 10
// baseline (speedup 1.0000x reference)
#include <cuda_runtime.h>
#include <math.h>
#include <stdint.h>

#define B_  4
#define N_  1024
#define C_  1024
#define H_  16
#define DH  64
#define BH  (B_*H_)
#define ROWS (BH*N_)

// ---------------- scratch -----------------------------------------------------
__device__ float g_q[(size_t)B_*H_*N_*DH];
__device__ float g_k[(size_t)B_*H_*N_*DH];
__device__ float g_v[(size_t)B_*H_*N_*DH];
__device__ float g_ctx[(size_t)B_*N_*C_];

// ---------------- bf16 3-pass helpers -----------------------------------------
// rn split: hi = rn_bf16(x) (|lo| <= 2^-9 |x|), lo = rn_bf16(x - hi).
__device__ __forceinline__ void split_pair_rn(float ve, float vo,
                                              uint32_t& hi, uint32_t& lo) {
    asm("cvt.rn.bf16x2.f32 %0, %1, %2;" : "=r"(hi) : "f"(vo), "f"(ve));
    float he  = __uint_as_float(hi << 16);
    float ho  = __uint_as_float(hi & 0xFFFF0000u);
    float le  = ve - he;
    float lof = vo - ho;
    asm("cvt.rn.bf16x2.f32 %0, %1, %2;" : "=r"(lo) : "f"(lof), "f"(le));
}
__device__ __forceinline__ void mma16(float c[4],
                                      uint32_t a0, uint32_t a1, uint32_t a2, uint32_t a3,
                                      uint32_t b0, uint32_t b1) {
    asm("mma.sync.aligned.m16n8k16.row.col.f32.bf16.bf16.f32 "
        "{%0,%1,%2,%3},{%4,%5,%6,%7},{%8,%9},{%0,%1,%2,%3};"
        : "+f"(c[0]), "+f"(c[1]), "+f"(c[2]), "+f"(c[3])
        : "r"(a0), "r"(a1), "r"(a2), "r"(a3), "r"(b0), "r"(b1));
}

// ============ GEMM: C = A[4096xK] @ W[KxN] + b (3x bf16 k16) ==================
// 64x128 CTA tile, warps 2x4 (warp tile 32x32), single buffer, 3 CTAs/SM.
__device__ __forceinline__ void gemm64_body(const float* __restrict__ A,
                                            const float* __restrict__ W,
                                            const float* __restrict__ bias,
                                            float* __restrict__ C,
                                            int head_mode)
{
    __shared__ uint32_t Ahs[64][12],  Als[64][12];    // [m][kpair]
    __shared__ uint32_t Whs[128][12], Wls[128][12];   // [n][kpair]

    const int K = C_, Nn = C_;
    int tid = threadIdx.x;
    int lane = tid & 31, wid = tid >> 5;
    int g = lane >> 2, qq = lane & 3;
    int wm = wid >> 2, wn = wid & 3;
    int row0 = blockIdx.y * 64;
    int col0 = blockIdx.x * 128;

    int ar = tid >> 2, ac = (tid & 3) * 4, c2 = (tid & 3) * 2;
    int rp = tid >> 5, wc = (tid & 31) * 4;

    float acc[2][4][4] = {};
    float4 pa, pw0, pw1;

    pa  = *(const float4*)&A[(size_t)(row0 + ar) * K + ac];
    pw0 = *(const float4*)&W[(size_t)(2 * rp) * Nn + col0 + wc];
    pw1 = *(const float4*)&W[(size_t)(2 * rp + 1) * Nn + col0 + wc];

    const int NB = K / 16;
    for (int kb = 0; kb < NB; kb++) {
        {
            uint32_t h0, l0, h1, l1;
            split_pair_rn(pa.x, pa.y, h0, l0);
            split_pair_rn(pa.z, pa.w, h1, l1);
            Ahs[ar][c2] = h0; Ahs[ar][c2 + 1] = h1;
            Als[ar][c2] = l0; Als[ar][c2 + 1] = l1;
        }
        {
            const float* e = (const float*)&pw0;
            const float* o = (const float*)&pw1;
            #pragma unroll
            for (int j = 0; j < 4; j++) {
                uint32_t hh, ll;
                split_pair_rn(e[j], o[j], hh, ll);
                Whs[wc + j][rp] = hh;
                Wls[wc + j][rp] = ll;
            }
        }
        __syncthreads();

        if (kb + 1 < NB) {
            int k0 = (kb + 1) * 16;
            pa  = *(const float4*)&A[(size_t)(row0 + ar) * K + k0 + ac];
            pw0 = *(const float4*)&W[(size_t)(k0 + 2 * rp) * Nn + col0 + wc];
            pw1 = *(const float4*)&W[(size_t)(k0 + 2 * rp + 1) * Nn + col0 + wc];
        }

        uint32_t bh0[4], bh1[4], bl0[4], bl1[4];
        #pragma unroll
        for (int fn = 0; fn < 4; fn++) {
            int col = wn * 32 + fn * 8 + g;
            bh0[fn] = Whs[col][qq];     bh1[fn] = Whs[col][qq + 4];
            bl0[fn] = Wls[col][qq];     bl1[fn] = Wls[col][qq + 4];
        }
        #pragma unroll
        for (int fm = 0; fm < 2; fm++) {
            int m = wm * 32 + fm * 16 + g;
            uint32_t ah[4], al[4];
            ah[0] = Ahs[m][qq];     ah[1] = Ahs[m + 8][qq];
            ah[2] = Ahs[m][qq + 4]; ah[3] = Ahs[m + 8][qq + 4];
            al[0] = Als[m][qq];     al[1] = Als[m + 8][qq];
            al[2] = Als[m][qq + 4]; al[3] = Als[m + 8][qq + 4];
            #pragma unroll
            for (int fn = 0; fn < 4; fn++)
                mma16(acc[fm][fn], ah[0], ah[1], ah[2], ah[3], bh0[fn], bh1[fn]);
            #pragma unroll
            for (int fn = 0; fn < 4; fn++)
                mma16(acc[fm][fn], ah[0], ah[1], ah[2], ah[3], bl0[fn], bl1[fn]);
            #pragma unroll
            for (int fn = 0; fn < 4; fn++)
                mma16(acc[fm][fn], al[0], al[1], al[2], al[3], bh0[fn], bh1[fn]);
        }
        __syncthreads();
    }

    #pragma unroll
    for (int fm = 0; fm < 2; fm++) {
        int rowA = row0 + wm * 32 + fm * 16 + g;
        #pragma unroll
        for (int fn = 0; fn < 4; fn++) {
            int col = col0 + wn * 32 + fn * 8 + 2 * qq;
            float2 p0, p1;
            p0.x = acc[fm][fn][0] + bias[col];
            p0.y = acc[fm][fn][1] + bias[col + 1];
            p1.x = acc[fm][fn][2] + bias[col];
            p1.y = acc[fm][fn][3] + bias[col + 1];
            if (head_mode) {
                int h = col >> 6, d = col & 63;
                int bb0 = rowA >> 10, n0 = rowA & 1023;
                int bb1 = (rowA + 8) >> 10, n1 = (rowA + 8) & 1023;
                *(float2*)&C[(((size_t)bb0 * H_ + h) * N_ + n0) * DH + d] = p0;
                *(float2*)&C[(((size_t)bb1 * H_ + h) * N_ + n1) * DH + d] = p1;
            } else {
                *(float2*)&C[(size_t)rowA * Nn + col] = p0;
                *(float2*)&C[(size_t)(rowA + 8) * Nn + col] = p1;
            }
        }
    }
}

__global__ void __launch_bounds__(256, 3)
qkv_kernel(const float* __restrict__ x,
           const float* __restrict__ Wq, const float* __restrict__ bq,
           const float* __restrict__ Wk, const float* __restrict__ bk,
           const float* __restrict__ Wv, const float* __restrict__ bv,
           float* __restrict__ q, float* __restrict__ k, float* __restrict__ v)
{
    int z = blockIdx.z;
    if (z == 0)      gemm64_body(x, Wq, bq, q, 1);
    else if (z == 1) gemm64_body(x, Wk, bk, k, 1);
    else             gemm64_body(x, Wv, bv, v, 1);
}

__global__ void __launch_bounds__(256, 3)
proj_kernel(const float* __restrict__ A, const float* __restrict__ W,
            const float* __restrict__ bias, float* __restrict__ C)
{
    gemm64_body(A, W, bias, C, 0);
}

// ============ scores: per (b,h), S = Q @ K^T * 0.125 (3x bf16 k16) ============
__global__ void __launch_bounds__(256, 2)
scores_kernel(const float* __restrict__ Q, const float* __restrict__ Km,
              float* __restrict__ S)
{
    __shared__ uint32_t Qp[128][20], Ql[128][20];
    __shared__ uint32_t Kp[128][20], Kl[128][20];

    int z = blockIdx.z;
    const float* Qb = Q  + (size_t)z * N_ * DH;
    const float* Kb = Km + (size_t)z * N_ * DH;

    int tid = threadIdx.x;
    int lane = tid & 31, wid = tid >> 5;
    int g = lane >> 2, qq = lane & 3;
    int wm = wid >> 2, wn = wid & 3;
    int row0 = blockIdx.y * 128;
    int col0 = blockIdx.x * 128;

    int r = tid >> 1;
    int cbase = (tid & 1) * 4;

    float acc[4][4][4] = {};

    #pragma unroll
    for (int kb = 0; kb < 2; kb++) {
        int k0 = kb * 32;
        #pragma unroll
        for (int j = 0; j < 4; j++) {
            int c = cbase + j;
            float4 vq = *(const float4*)&Qb[(size_t)(row0 + r) * DH + k0 + c * 4];
            float4 vk = *(const float4*)&Kb[(size_t)(col0 + r) * DH + k0 + c * 4];
            uint32_t h0, l0, h1, l1;
            split_pair_rn(vq.x, vq.y, h0, l0);
            split_pair_rn(vq.z, vq.w, h1, l1);
            Qp[r][c * 2] = h0; Qp[r][c * 2 + 1] = h1;
            Ql[r][c * 2] = l0; Ql[r][c * 2 + 1] = l1;
            split_pair_rn(vk.x, vk.y, h0, l0);
            split_pair_rn(vk.z, vk.w, h1, l1);
            Kp[r][c * 2] = h0; Kp[r][c * 2 + 1] = h1;
            Kl[r][c * 2] = l0; Kl[r][c * 2 + 1] = l1;
        }
        __syncthreads();

        #pragma unroll
        for (int ks = 0; ks < 2; ks++) {
            int pb = ks * 8;
            uint32_t bh0[4], bh1[4], bl0[4], bl1[4];
            #pragma unroll
            for (int fn = 0; fn < 4; fn++) {
                int col = wn * 32 + fn * 8 + g;
                bh0[fn] = Kp[col][pb + qq];     bh1[fn] = Kp[col][pb + qq + 4];
                bl0[fn] = Kl[col][pb + qq];     bl1[fn] = Kl[col][pb + qq + 4];
            }
            #pragma unroll
            for (int fm = 0; fm < 4; fm++) {
                int m = wm * 64 + fm * 16 + g;
                uint32_t ah[4], al[4];
                ah[0] = Qp[m][pb + qq];     ah[1] = Qp[m + 8][pb + qq];
                ah[2] = Qp[m][pb + qq + 4]; ah[3] = Qp[m + 8][pb + qq + 4];
                al[0] = Ql[m][pb + qq];     al[1] = Ql[m + 8][pb + qq];
                al[2] = Ql[m][pb + qq + 4]; al[3] = Ql[m + 8][pb + qq + 4];
                #pragma unroll
                for (int fn = 0; fn < 4; fn++)
                    mma16(acc[fm][fn], ah[0], ah[1], ah[2], ah[3], bh0[fn], bh1[fn]);
                #pragma unroll
                for (int fn = 0; fn < 4; fn++)
                    mma16(acc[fm][fn], ah[0], ah[1], ah[2], ah[3], bl0[fn], bl1[fn]);
                #pragma unroll
                for (int fn = 0; fn < 4; fn++)
                    mma16(acc[fm][fn], al[0], al[1], al[2], al[3], bh0[fn], bh1[fn]);
            }
        }
        if (kb == 0) __syncthreads();
    }

    float* Sb = S + (size_t)z * N_ * N_;
    #pragma unroll
    for (int fm = 0; fm < 4; fm++) {
        int rowA = row0 + wm * 64 + fm * 16 + g;
        #pragma unroll
        for (int fn = 0; fn < 4; fn++) {
            int col = col0 + wn * 32 + fn * 8 + 2 * qq;
            float2 p0, p1;
            p0.x = acc[fm][fn][0] * 0.125f;
            p0.y = acc[fm][fn][1] * 0.125f;
            p1.x = acc[fm][fn][2] * 0.125f;
            p1.y = acc[fm][fn][3] * 0.125f;
            *(float2*)&Sb[(size_t)rowA * N_ + col] = p0;
            *(float2*)&Sb[(size_t)(rowA + 8) * N_ + col] = p1;
        }
    }
}

// ============ entmax: 10 bisection iters + exact quadratic finish =============
__global__ void entmax_kernel(float* __restrict__ attn)
{
    int warp = threadIdx.x >> 5;
    int lane = threadIdx.x & 31;
    size_t row = (size_t)blockIdx.x * 8 + warp;
    float* S = attn + row * N_;

    float xa[32];
    float mx = -INFINITY;
    #pragma unroll
    for (int i = 0; i < 32; i++) {
        float v = S[i * 32 + lane] * 0.5f;
        xa[i] = v;
        mx = fmaxf(mx, v);
    }
    #pragma unroll
    for (int o = 16; o; o >>= 1)
        mx = fmaxf(mx, __shfl_xor_sync(0xFFFFFFFFu, mx, o));

    float tau_lo = mx - 1.0f;
    float dm = 1.0f - 0.03125f;

    float f_lo = 0.0f;
    #pragma unroll
    for (int i = 0; i < 32; i++) {
        float t = fmaxf(xa[i] - tau_lo, 0.0f);
        f_lo = fmaf(t, t, f_lo);
    }
    #pragma unroll
    for (int o = 16; o; o >>= 1)
        f_lo += __shfl_xor_sync(0xFFFFFFFFu, f_lo, o);
    f_lo -= 1.0f;

    for (int it = 0; it < 10; it++) {
        dm *= 0.5f;
        float tau_m = tau_lo + dm;
        float f = 0.0f;
        #pragma unroll
        for (int i = 0; i < 32; i++) {
            float t = fmaxf(xa[i] - tau_m, 0.0f);
            f = fmaf(t, t, f);
        }
        #pragma unroll
        for (int o = 16; o; o >>= 1)
            f += __shfl_xor_sync(0xFFFFFFFFu, f, o);
        f -= 1.0f;
        if (f * f_lo >= 0.0f) tau_lo = tau_m;
    }

    int   cnt = 0;
    float S1 = 0.0f, S2 = 0.0f;
    #pragma unroll
    for (int i = 0; i < 32; i++) {
        if (xa[i] > tau_lo) {
            cnt += 1;
            S1 += xa[i];
            S2 = fmaf(xa[i], xa[i], S2);
        }
    }
    #pragma unroll
    for (int o = 16; o; o >>= 1) {
        cnt += __shfl_xor_sync(0xFFFFFFFFu, cnt, o);
        S1  += __shfl_xor_sync(0xFFFFFFFFu, S1, o);
        S2  += __shfl_xor_sync(0xFFFFFFFFu, S2, o);
    }
    float kf = (float)cnt;
    float disc = fmaxf(fmaf(S1, S1, -kf * (S2 - 1.0f)), 0.0f);
    float tau = (S1 - sqrtf(disc)) / kf;
    tau = fminf(fmaxf(tau, tau_lo), tau_lo + dm);

    float p[32];
    float s = 0.0f;
    #pragma unroll
    for (int i = 0; i < 32; i++) {
        float t = fmaxf(xa[i] - tau, 0.0f);
        p[i] = t * t;
        s += p[i];
    }
    #pragma unroll
    for (int o = 16; o; o >>= 1)
        s += __shfl_xor_sync(0xFFFFFFFFu, s, o);
    float inv = 1.0f / s;

    #pragma unroll
    for (int i = 0; i < 32; i++)
        S[i * 32 + lane] = p[i] * inv;
}

// ============ ctx = attn @ V per (b,h): 3x bf16 m16n8k16 (R6 body) ============
__global__ void __launch_bounds__(256, 3)
attnv_kernel(const float* __restrict__ Attn, const float* __restrict__ V,
             float* __restrict__ ctx)
{
    __shared__ uint32_t Ahs[128][12], Als[128][12];   // [m][kpair]
    __shared__ uint32_t Vhs[64][12],  Vls[64][12];    // [d][kpair]

    int z = blockIdx.z;
    int bb = z >> 4, h = z & 15;
    const float* Ab = Attn + (size_t)z * N_ * N_;
    const float* Vb = V    + (size_t)z * N_ * DH;

    int tid = threadIdx.x;
    int lane = tid & 31, wid = tid >> 5;
    int g = lane >> 2, qq = lane & 3;
    int wm = wid >> 1, wn = wid & 1;
    int row0 = blockIdx.y * 128;

    int ar = tid >> 2, ac = (tid & 3) * 4, c2 = (tid & 3) * 2;
    int rp = (tid & 127) >> 4, vc = (tid & 15) * 4;
    bool vload = tid < 128;

    float acc[2][4][4] = {};
    float4 pa[2], pv0, pv1;

    #pragma unroll
    for (int i = 0; i < 2; i++)
        pa[i] = *(const float4*)&Ab[(size_t)(row0 + ar + i * 64) * N_ + ac];
    if (vload) {
        pv0 = *(const float4*)&Vb[(size_t)(2 * rp) * DH + vc];
        pv1 = *(const float4*)&Vb[(size_t)(2 * rp + 1) * DH + vc];
    }

    const int NB = N_ / 16;
    for (int kb = 0; kb < NB; kb++) {
        #pragma unroll
        for (int i = 0; i < 2; i++) {
            uint32_t h0, l0, h1, l1;
            split_pair_rn(pa[i].x, pa[i].y, h0, l0);
            split_pair_rn(pa[i].z, pa[i].w, h1, l1);
            int r = ar + i * 64;
            Ahs[r][c2] = h0; Ahs[r][c2 + 1] = h1;
            Als[r][c2] = l0; Als[r][c2 + 1] = l1;
        }
        if (vload) {
            const float* e = (const float*)&pv0;
            const float* o = (const float*)&pv1;
            #pragma unroll
            for (int j = 0; j < 4; j++) {
                uint32_t hh, ll;
                split_pair_rn(e[j], o[j], hh, ll);
                Vhs[vc + j][rp] = hh;
                Vls[vc + j][rp] = ll;
            }
        }
        __syncthreads();

        if (kb + 1 < NB) {
            int k0 = (kb + 1) * 16;
            #pragma unroll
            for (int i = 0; i < 2; i++)
                pa[i] = *(const float4*)&Ab[(size_t)(row0 + ar + i * 64) * N_ + k0 + ac];
            if (vload) {
                pv0 = *(const float4*)&Vb[(size_t)(k0 + 2 * rp) * DH + vc];
                pv1 = *(const float4*)&Vb[(size_t)(k0 + 2 * rp + 1) * DH + vc];
            }
        }

        uint32_t bh0[4], bh1[4], bl0[4], bl1[4];
        #pragma unroll
        for (int fn = 0; fn < 4; fn++) {
            int col = wn * 32 + fn * 8 + g;
            bh0[fn] = Vhs[col][qq];     bh1[fn] = Vhs[col][qq + 4];
            bl0[fn] = Vls[col][qq];     bl1[fn] = Vls[col][qq + 4];
        }
        #pragma unroll
        for (int fm = 0; fm < 2; fm++) {
            int m = wm * 32 + fm * 16 + g;
            uint32_t ah[4], al[4];
            ah[0] = Ahs[m][qq];     ah[1] = Ahs[m + 8][qq];
            ah[2] = Ahs[m][qq + 4]; ah[3] = Ahs[m + 8][qq + 4];
            al[0] = Als[m][qq];     al[1] = Als[m + 8][qq];
            al[2] = Als[m][qq + 4]; al[3] = Als[m + 8][qq + 4];
            #pragma unroll
            for (int fn = 0; fn < 4; fn++)
                mma16(acc[fm][fn], ah[0], ah[1], ah[2], ah[3], bh0[fn], bh1[fn]);
            #pragma unroll
            for (int fn = 0; fn < 4; fn++)
                mma16(acc[fm][fn], ah[0], ah[1], ah[2], ah[3], bl0[fn], bl1[fn]);
            #pragma unroll
            for (int fn = 0; fn < 4; fn++)
                mma16(acc[fm][fn], al[0], al[1], al[2], al[3], bh0[fn], bh1[fn]);
        }
        __syncthreads();
    }

    #pragma unroll
    for (int fm = 0; fm < 2; fm++) {
        int n = row0 + wm * 32 + fm * 16 + g;
        #pragma unroll
        for (int fn = 0; fn < 4; fn++) {
            int d = wn * 32 + fn * 8 + 2 * qq;
            float2 p0, p1;
            p0.x = acc[fm][fn][0]; p0.y = acc[fm][fn][1];
            p1.x = acc[fm][fn][2]; p1.y = acc[fm][fn][3];
            *(float2*)&ctx[((size_t)bb * N_ + n) * C_ + h * DH + d] = p0;
            *(float2*)&ctx[((size_t)bb * N_ + n + 8) * C_ + h * DH + d] = p1;
        }
    }
}

// ============ launcher ========================================================
extern "C" void kernel_launch(void* const* d_in, const int* in_sizes, int n_in,
                              void* d_out, int out_size)
{
    const float* x  = (const float*)d_in[0];
    const float* Wq = (const float*)d_in[1];
    const float* bq = (const float*)d_in[2];
    const float* Wk = (const float*)d_in[3];
    const float* bk = (const float*)d_in[4];
    const float* Wv = (const float*)d_in[5];
    const float* bv = (const float*)d_in[6];
    const float* Wo = (const float*)d_in[7];
    const float* bo = (const float*)d_in[8];

    float* out = (float*)d_out;
    const size_t attn_elems = (size_t)B_ * H_ * N_ * N_;
    float* attn = out + ((size_t)out_size - attn_elems);

    float *q, *k, *v, *ctx;
    cudaGetSymbolAddress((void**)&q,   g_q);
    cudaGetSymbolAddress((void**)&k,   g_k);
    cudaGetSymbolAddress((void**)&v,   g_v);
    cudaGetSymbolAddress((void**)&ctx, g_ctx);

    dim3 blk(256);

    qkv_kernel<<<dim3(8, 64, 3), blk>>>(x, Wq, bq, Wk, bk, Wv, bv, q, k, v);
    scores_kernel<<<dim3(8, 8, BH), blk>>>(q, k, attn);
    entmax_kernel<<<dim3(ROWS / 8), blk>>>(attn);
    attnv_kernel<<<dim3(1, 8, BH), blk>>>(attn, v, ctx);
    proj_kernel<<<dim3(8, 64), blk>>>(ctx, Wo, bo, out);
}

// round 13
// speedup vs baseline: 1.4254x; 1.4254x over previous
#include <cuda_runtime.h>
#include <math.h>
#include <stdint.h>

#define B_  4
#define N_  1024
#define C_  1024
#define H_  16
#define DH  64
#define BH  (B_*H_)
#define ROWS (BH*N_)
#define KP  512            // kpairs per 1024-length row

// ---------------- scratch -----------------------------------------------------
__device__ float g_q[(size_t)B_*H_*N_*DH];
__device__ float g_k[(size_t)B_*H_*N_*DH];
__device__ float g_v[(size_t)B_*H_*N_*DH];
// pre-split bf16 kpair arrays
__device__ uint32_t g_x_h[(size_t)4096*KP],  g_x_l[(size_t)4096*KP];
__device__ uint32_t g_wt_h[4][(size_t)1024*KP], g_wt_l[4][(size_t)1024*KP];
__device__ uint32_t g_ctx_h[(size_t)4096*KP], g_ctx_l[(size_t)4096*KP];

// ---------------- bf16 3-pass helpers -----------------------------------------
__device__ __forceinline__ void split_pair_rn(float ve, float vo,
                                              uint32_t& hi, uint32_t& lo) {
    asm("cvt.rn.bf16x2.f32 %0, %1, %2;" : "=r"(hi) : "f"(vo), "f"(ve));
    float he  = __uint_as_float(hi << 16);
    float ho  = __uint_as_float(hi & 0xFFFF0000u);
    float le  = ve - he;
    float lof = vo - ho;
    asm("cvt.rn.bf16x2.f32 %0, %1, %2;" : "=r"(lo) : "f"(lof), "f"(le));
}
__device__ __forceinline__ void mma16(float c[4],
                                      uint32_t a0, uint32_t a1, uint32_t a2, uint32_t a3,
                                      uint32_t b0, uint32_t b1) {
    asm("mma.sync.aligned.m16n8k16.row.col.f32.bf16.bf16.f32 "
        "{%0,%1,%2,%3},{%4,%5,%6,%7},{%8,%9},{%0,%1,%2,%3};"
        : "+f"(c[0]), "+f"(c[1]), "+f"(c[2]), "+f"(c[3])
        : "r"(a0), "r"(a1), "r"(a2), "r"(a3), "r"(b0), "r"(b1));
}

// ============ one-time converts ===============================================
// x: [4096][1024] fp32 -> hi/lo kpair arrays (one float4 per thread)
__global__ void convert_x_kernel(const float* __restrict__ x)
{
    size_t i = (size_t)blockIdx.x * 256 + threadIdx.x;
    float4 v = ((const float4*)x)[i];
    uint32_t h0, l0, h1, l1;
    split_pair_rn(v.x, v.y, h0, l0);
    split_pair_rn(v.z, v.w, h1, l1);
    ((uint2*)g_x_h)[i] = make_uint2(h0, h1);
    ((uint2*)g_x_l)[i] = make_uint2(l0, l1);
}

// W: [1024k][1024n] fp32 -> transposed [n][kpair] hi/lo (z selects weight)
__global__ void convert_w_kernel(const float* __restrict__ W0,
                                 const float* __restrict__ W1,
                                 const float* __restrict__ W2,
                                 const float* __restrict__ W3)
{
    // row stride 68 floats = 272 B (16-divisible) so float4 stores stay aligned
    __shared__ __align__(16) float s[64][68];
    const float* W = (blockIdx.z == 0) ? W0 : (blockIdx.z == 1) ? W1
                   : (blockIdx.z == 2) ? W2 : W3;
    uint32_t* outH = g_wt_h[blockIdx.z];
    uint32_t* outL = g_wt_l[blockIdx.z];
    int t = threadIdx.x;
    int k0 = blockIdx.x * 64, n0 = blockIdx.y * 64;

    #pragma unroll
    for (int i = 0; i < 4; i++) {
        int k = (t >> 4) + i * 16, n4 = (t & 15) * 4;
        *(float4*)&s[k][n4] = *(const float4*)&W[(size_t)(k0 + k) * C_ + n0 + n4];
    }
    __syncthreads();

    #pragma unroll
    for (int j = 0; j < 2; j++) {
        int idx = t + j * 256;
        int nn = idx >> 3, qd = idx & 7;
        uint4 h4, l4;
        uint32_t* hp = (uint32_t*)&h4;
        uint32_t* lp = (uint32_t*)&l4;
        #pragma unroll
        for (int e = 0; e < 4; e++) {
            int kpl = 4 * qd + e;
            split_pair_rn(s[2 * kpl][nn], s[2 * kpl + 1][nn], hp[e], lp[e]);
        }
        size_t off = (size_t)(n0 + nn) * KP + (k0 >> 1) + 4 * qd;
        *(uint4*)&outH[off] = h4;
        *(uint4*)&outL[off] = l4;
    }
}

// ============ GEMM v2: pre-split bf16 operands, 128x128, BK=32 ================
__device__ __forceinline__ void gemm2_body(const uint32_t* __restrict__ AgH,
                                           const uint32_t* __restrict__ AgL,
                                           const uint32_t* __restrict__ WgH,
                                           const uint32_t* __restrict__ WgL,
                                           const float* __restrict__ bias,
                                           float* __restrict__ C,
                                           int head_mode)
{
    // row stride 20 u32 = 80 B (16-divisible); __align__(16) makes uint4 ops legal
    __shared__ __align__(16) uint32_t Ah[128][20], Al[128][20];   // [m][kpair]
    __shared__ __align__(16) uint32_t Wh[128][20], Wl[128][20];   // [n][kpair]

    int tid = threadIdx.x;
    int lane = tid & 31, wid = tid >> 5;
    int g = lane >> 2, qq = lane & 3;
    int wm = wid >> 2, wn = wid & 3;
    int row0 = blockIdx.y * 128;
    int col0 = blockIdx.x * 128;

    // fill: 256 threads cover 128 rows x 16 kpairs (2 uint4 per array each)
    int fr = tid >> 1, fq = (tid & 1) * 8;

    float acc[4][4][4] = {};

    for (int kb = 0; kb < 32; kb++) {          // 32 blocks of 16 kpairs (K=1024)
        size_t abase = (size_t)(row0 + fr) * KP + kb * 16 + fq;
        size_t wbase = (size_t)(col0 + fr) * KP + kb * 16 + fq;
        *(uint4*)&Ah[fr][fq]     = *(const uint4*)&AgH[abase];
        *(uint4*)&Ah[fr][fq + 4] = *(const uint4*)&AgH[abase + 4];
        *(uint4*)&Al[fr][fq]     = *(const uint4*)&AgL[abase];
        *(uint4*)&Al[fr][fq + 4] = *(const uint4*)&AgL[abase + 4];
        *(uint4*)&Wh[fr][fq]     = *(const uint4*)&WgH[wbase];
        *(uint4*)&Wh[fr][fq + 4] = *(const uint4*)&WgH[wbase + 4];
        *(uint4*)&Wl[fr][fq]     = *(const uint4*)&WgL[wbase];
        *(uint4*)&Wl[fr][fq + 4] = *(const uint4*)&WgL[wbase + 4];
        __syncthreads();

        #pragma unroll
        for (int s = 0; s < 2; s++) {
            int pb = s * 8;
            uint32_t bh0[4], bh1[4], bl0[4], bl1[4];
            #pragma unroll
            for (int fn = 0; fn < 4; fn++) {
                int col = wn * 32 + fn * 8 + g;
                bh0[fn] = Wh[col][pb + qq];     bh1[fn] = Wh[col][pb + qq + 4];
                bl0[fn] = Wl[col][pb + qq];     bl1[fn] = Wl[col][pb + qq + 4];
            }
            #pragma unroll
            for (int fm = 0; fm < 4; fm++) {
                int m = wm * 64 + fm * 16 + g;
                uint32_t ah[4], al[4];
                ah[0] = Ah[m][pb + qq];     ah[1] = Ah[m + 8][pb + qq];
                ah[2] = Ah[m][pb + qq + 4]; ah[3] = Ah[m + 8][pb + qq + 4];
                al[0] = Al[m][pb + qq];     al[1] = Al[m + 8][pb + qq];
                al[2] = Al[m][pb + qq + 4]; al[3] = Al[m + 8][pb + qq + 4];
                #pragma unroll
                for (int fn = 0; fn < 4; fn++)
                    mma16(acc[fm][fn], ah[0], ah[1], ah[2], ah[3], bh0[fn], bh1[fn]);
                #pragma unroll
                for (int fn = 0; fn < 4; fn++)
                    mma16(acc[fm][fn], ah[0], ah[1], ah[2], ah[3], bl0[fn], bl1[fn]);
                #pragma unroll
                for (int fn = 0; fn < 4; fn++)
                    mma16(acc[fm][fn], al[0], al[1], al[2], al[3], bh0[fn], bh1[fn]);
            }
        }
        __syncthreads();
    }

    #pragma unroll
    for (int fm = 0; fm < 4; fm++) {
        int rowA = row0 + wm * 64 + fm * 16 + g;
        #pragma unroll
        for (int fn = 0; fn < 4; fn++) {
            int col = col0 + wn * 32 + fn * 8 + 2 * qq;
            float2 p0, p1;
            p0.x = acc[fm][fn][0] + bias[col];
            p0.y = acc[fm][fn][1] + bias[col + 1];
            p1.x = acc[fm][fn][2] + bias[col];
            p1.y = acc[fm][fn][3] + bias[col + 1];
            if (head_mode) {
                int h = col >> 6, d = col & 63;
                int bb0 = rowA >> 10, n0 = rowA & 1023;
                int bb1 = (rowA + 8) >> 10, n1 = (rowA + 8) & 1023;
                *(float2*)&C[(((size_t)bb0 * H_ + h) * N_ + n0) * DH + d] = p0;
                *(float2*)&C[(((size_t)bb1 * H_ + h) * N_ + n1) * DH + d] = p1;
            } else {
                *(float2*)&C[(size_t)rowA * C_ + col] = p0;
                *(float2*)&C[(size_t)(rowA + 8) * C_ + col] = p1;
            }
        }
    }
}

__global__ void __launch_bounds__(256, 2)
qkv2_kernel(const float* __restrict__ bq, const float* __restrict__ bk,
            const float* __restrict__ bv,
            float* __restrict__ q, float* __restrict__ k, float* __restrict__ v)
{
    int z = blockIdx.z;
    if (z == 0)      gemm2_body(g_x_h, g_x_l, g_wt_h[0], g_wt_l[0], bq, q, 1);
    else if (z == 1) gemm2_body(g_x_h, g_x_l, g_wt_h[1], g_wt_l[1], bk, k, 1);
    else             gemm2_body(g_x_h, g_x_l, g_wt_h[2], g_wt_l[2], bv, v, 1);
}

__global__ void __launch_bounds__(256, 2)
proj2_kernel(const float* __restrict__ bo, float* __restrict__ out)
{
    gemm2_body(g_ctx_h, g_ctx_l, g_wt_h[3], g_wt_l[3], bo, out, 0);
}

// ============ scores: per (b,h), S = Q @ K^T * 0.125 (3x bf16 k16) ============
__global__ void __launch_bounds__(256, 2)
scores_kernel(const float* __restrict__ Q, const float* __restrict__ Km,
              float* __restrict__ S)
{
    __shared__ uint32_t Qp[128][20], Ql[128][20];
    __shared__ uint32_t Kp[128][20], Kl[128][20];

    int z = blockIdx.z;
    const float* Qb = Q  + (size_t)z * N_ * DH;
    const float* Kb = Km + (size_t)z * N_ * DH;

    int tid = threadIdx.x;
    int lane = tid & 31, wid = tid >> 5;
    int g = lane >> 2, qq = lane & 3;
    int wm = wid >> 2, wn = wid & 3;
    int row0 = blockIdx.y * 128;
    int col0 = blockIdx.x * 128;

    int r = tid >> 1;
    int cbase = (tid & 1) * 4;

    float acc[4][4][4] = {};

    #pragma unroll
    for (int kb = 0; kb < 2; kb++) {
        int k0 = kb * 32;
        #pragma unroll
        for (int j = 0; j < 4; j++) {
            int c = cbase + j;
            float4 vq = *(const float4*)&Qb[(size_t)(row0 + r) * DH + k0 + c * 4];
            float4 vk = *(const float4*)&Kb[(size_t)(col0 + r) * DH + k0 + c * 4];
            uint32_t h0, l0, h1, l1;
            split_pair_rn(vq.x, vq.y, h0, l0);
            split_pair_rn(vq.z, vq.w, h1, l1);
            Qp[r][c * 2] = h0; Qp[r][c * 2 + 1] = h1;
            Ql[r][c * 2] = l0; Ql[r][c * 2 + 1] = l1;
            split_pair_rn(vk.x, vk.y, h0, l0);
            split_pair_rn(vk.z, vk.w, h1, l1);
            Kp[r][c * 2] = h0; Kp[r][c * 2 + 1] = h1;
            Kl[r][c * 2] = l0; Kl[r][c * 2 + 1] = l1;
        }
        __syncthreads();

        #pragma unroll
        for (int ks = 0; ks < 2; ks++) {
            int pb = ks * 8;
            uint32_t bh0[4], bh1[4], bl0[4], bl1[4];
            #pragma unroll
            for (int fn = 0; fn < 4; fn++) {
                int col = wn * 32 + fn * 8 + g;
                bh0[fn] = Kp[col][pb + qq];     bh1[fn] = Kp[col][pb + qq + 4];
                bl0[fn] = Kl[col][pb + qq];     bl1[fn] = Kl[col][pb + qq + 4];
            }
            #pragma unroll
            for (int fm = 0; fm < 4; fm++) {
                int m = wm * 64 + fm * 16 + g;
                uint32_t ah[4], al[4];
                ah[0] = Qp[m][pb + qq];     ah[1] = Qp[m + 8][pb + qq];
                ah[2] = Qp[m][pb + qq + 4]; ah[3] = Qp[m + 8][pb + qq + 4];
                al[0] = Ql[m][pb + qq];     al[1] = Ql[m + 8][pb + qq];
                al[2] = Ql[m][pb + qq + 4]; al[3] = Ql[m + 8][pb + qq + 4];
                #pragma unroll
                for (int fn = 0; fn < 4; fn++)
                    mma16(acc[fm][fn], ah[0], ah[1], ah[2], ah[3], bh0[fn], bh1[fn]);
                #pragma unroll
                for (int fn = 0; fn < 4; fn++)
                    mma16(acc[fm][fn], ah[0], ah[1], ah[2], ah[3], bl0[fn], bl1[fn]);
                #pragma unroll
                for (int fn = 0; fn < 4; fn++)
                    mma16(acc[fm][fn], al[0], al[1], al[2], al[3], bh0[fn], bh1[fn]);
            }
        }
        if (kb == 0) __syncthreads();
    }

    float* Sb = S + (size_t)z * N_ * N_;
    #pragma unroll
    for (int fm = 0; fm < 4; fm++) {
        int rowA = row0 + wm * 64 + fm * 16 + g;
        #pragma unroll
        for (int fn = 0; fn < 4; fn++) {
            int col = col0 + wn * 32 + fn * 8 + 2 * qq;
            float2 p0, p1;
            p0.x = acc[fm][fn][0] * 0.125f;
            p0.y = acc[fm][fn][1] * 0.125f;
            p1.x = acc[fm][fn][2] * 0.125f;
            p1.y = acc[fm][fn][3] * 0.125f;
            *(float2*)&Sb[(size_t)rowA * N_ + col] = p0;
            *(float2*)&Sb[(size_t)(rowA + 8) * N_ + col] = p1;
        }
    }
}

// ============ entmax: 10 bisection iters + exact quadratic finish =============
__global__ void entmax_kernel(float* __restrict__ attn)
{
    int warp = threadIdx.x >> 5;
    int lane = threadIdx.x & 31;
    size_t row = (size_t)blockIdx.x * 8 + warp;
    float* S = attn + row * N_;

    float xa[32];
    float mx = -INFINITY;
    #pragma unroll
    for (int i = 0; i < 32; i++) {
        float v = S[i * 32 + lane] * 0.5f;
        xa[i] = v;
        mx = fmaxf(mx, v);
    }
    #pragma unroll
    for (int o = 16; o; o >>= 1)
        mx = fmaxf(mx, __shfl_xor_sync(0xFFFFFFFFu, mx, o));

    float tau_lo = mx - 1.0f;
    float dm = 1.0f - 0.03125f;

    float f_lo = 0.0f;
    #pragma unroll
    for (int i = 0; i < 32; i++) {
        float t = fmaxf(xa[i] - tau_lo, 0.0f);
        f_lo = fmaf(t, t, f_lo);
    }
    #pragma unroll
    for (int o = 16; o; o >>= 1)
        f_lo += __shfl_xor_sync(0xFFFFFFFFu, f_lo, o);
    f_lo -= 1.0f;

    for (int it = 0; it < 10; it++) {
        dm *= 0.5f;
        float tau_m = tau_lo + dm;
        float f = 0.0f;
        #pragma unroll
        for (int i = 0; i < 32; i++) {
            float t = fmaxf(xa[i] - tau_m, 0.0f);
            f = fmaf(t, t, f);
        }
        #pragma unroll
        for (int o = 16; o; o >>= 1)
            f += __shfl_xor_sync(0xFFFFFFFFu, f, o);
        f -= 1.0f;
        if (f * f_lo >= 0.0f) tau_lo = tau_m;
    }

    int   cnt = 0;
    float S1 = 0.0f, S2 = 0.0f;
    #pragma unroll
    for (int i = 0; i < 32; i++) {
        if (xa[i] > tau_lo) {
            cnt += 1;
            S1 += xa[i];
            S2 = fmaf(xa[i], xa[i], S2);
        }
    }
    #pragma unroll
    for (int o = 16; o; o >>= 1) {
        cnt += __shfl_xor_sync(0xFFFFFFFFu, cnt, o);
        S1  += __shfl_xor_sync(0xFFFFFFFFu, S1, o);
        S2  += __shfl_xor_sync(0xFFFFFFFFu, S2, o);
    }
    float kf = (float)cnt;
    float disc = fmaxf(fmaf(S1, S1, -kf * (S2 - 1.0f)), 0.0f);
    float tau = (S1 - sqrtf(disc)) / kf;
    tau = fminf(fmaxf(tau, tau_lo), tau_lo + dm);

    float p[32];
    float s = 0.0f;
    #pragma unroll
    for (int i = 0; i < 32; i++) {
        float t = fmaxf(xa[i] - tau, 0.0f);
        p[i] = t * t;
        s += p[i];
    }
    #pragma unroll
    for (int o = 16; o; o >>= 1)
        s += __shfl_xor_sync(0xFFFFFFFFu, s, o);
    float inv = 1.0f / s;

    #pragma unroll
    for (int i = 0; i < 32; i++)
        S[i * 32 + lane] = p[i] * inv;
}

// ============ ctx = attn @ V per (b,h): 3x bf16 k16 (R6 body) =================
// epilogue writes ctx as pre-split bf16 kpairs for proj2.
__global__ void __launch_bounds__(256, 2)
attnv_kernel(const float* __restrict__ Attn, const float* __restrict__ V)
{
    __shared__ uint32_t Ahs[128][12], Als[128][12];
    __shared__ uint32_t Vhs[64][12],  Vls[64][12];

    int z = blockIdx.z;
    int bb = z >> 4, h = z & 15;
    const float* Ab = Attn + (size_t)z * N_ * N_;
    const float* Vb = V    + (size_t)z * N_ * DH;

    int tid = threadIdx.x;
    int lane = tid & 31, wid = tid >> 5;
    int g = lane >> 2, qq = lane & 3;
    int wm = wid >> 1, wn = wid & 1;
    int row0 = blockIdx.y * 128;

    int ar = tid >> 2, ac = (tid & 3) * 4, c2 = (tid & 3) * 2;
    int rp = (tid & 127) >> 4, vc = (tid & 15) * 4;
    bool vload = tid < 128;

    float acc[2][4][4] = {};
    float4 pa[2], pv0, pv1;

    #pragma unroll
    for (int i = 0; i < 2; i++)
        pa[i] = *(const float4*)&Ab[(size_t)(row0 + ar + i * 64) * N_ + ac];
    if (vload) {
        pv0 = *(const float4*)&Vb[(size_t)(2 * rp) * DH + vc];
        pv1 = *(const float4*)&Vb[(size_t)(2 * rp + 1) * DH + vc];
    }

    const int NB = N_ / 16;
    for (int kb = 0; kb < NB; kb++) {
        #pragma unroll
        for (int i = 0; i < 2; i++) {
            uint32_t h0, l0, h1, l1;
            split_pair_rn(pa[i].x, pa[i].y, h0, l0);
            split_pair_rn(pa[i].z, pa[i].w, h1, l1);
            int r = ar + i * 64;
            Ahs[r][c2] = h0; Ahs[r][c2 + 1] = h1;
            Als[r][c2] = l0; Als[r][c2 + 1] = l1;
        }
        if (vload) {
            const float* e = (const float*)&pv0;
            const float* o = (const float*)&pv1;
            #pragma unroll
            for (int j = 0; j < 4; j++) {
                uint32_t hh, ll;
                split_pair_rn(e[j], o[j], hh, ll);
                Vhs[vc + j][rp] = hh;
                Vls[vc + j][rp] = ll;
            }
        }
        __syncthreads();

        if (kb + 1 < NB) {
            int k0 = (kb + 1) * 16;
            #pragma unroll
            for (int i = 0; i < 2; i++)
                pa[i] = *(const float4*)&Ab[(size_t)(row0 + ar + i * 64) * N_ + k0 + ac];
            if (vload) {
                pv0 = *(const float4*)&Vb[(size_t)(k0 + 2 * rp) * DH + vc];
                pv1 = *(const float4*)&Vb[(size_t)(k0 + 2 * rp + 1) * DH + vc];
            }
        }

        uint32_t bh0[4], bh1[4], bl0[4], bl1[4];
        #pragma unroll
        for (int fn = 0; fn < 4; fn++) {
            int col = wn * 32 + fn * 8 + g;
            bh0[fn] = Vhs[col][qq];     bh1[fn] = Vhs[col][qq + 4];
            bl0[fn] = Vls[col][qq];     bl1[fn] = Vls[col][qq + 4];
        }
        #pragma unroll
        for (int fm = 0; fm < 2; fm++) {
            int m = wm * 32 + fm * 16 + g;
            uint32_t ah[4], al[4];
            ah[0] = Ahs[m][qq];     ah[1] = Ahs[m + 8][qq];
            ah[2] = Ahs[m][qq + 4]; ah[3] = Ahs[m + 8][qq + 4];
            al[0] = Als[m][qq];     al[1] = Als[m + 8][qq];
            al[2] = Als[m][qq + 4]; al[3] = Als[m + 8][qq + 4];
            #pragma unroll
            for (int fn = 0; fn < 4; fn++)
                mma16(acc[fm][fn], ah[0], ah[1], ah[2], ah[3], bh0[fn], bh1[fn]);
            #pragma unroll
            for (int fn = 0; fn < 4; fn++)
                mma16(acc[fm][fn], ah[0], ah[1], ah[2], ah[3], bl0[fn], bl1[fn]);
            #pragma unroll
            for (int fn = 0; fn < 4; fn++)
                mma16(acc[fm][fn], al[0], al[1], al[2], al[3], bh0[fn], bh1[fn]);
        }
        __syncthreads();
    }

    // epilogue: split ctx to bf16 kpairs for proj2
    #pragma unroll
    for (int fm = 0; fm < 2; fm++) {
        int n = row0 + wm * 32 + fm * 16 + g;
        #pragma unroll
        for (int fn = 0; fn < 4; fn++) {
            int d = wn * 32 + fn * 8 + 2 * qq;
            uint32_t h0, l0, h1, l1;
            split_pair_rn(acc[fm][fn][0], acc[fm][fn][1], h0, l0);
            split_pair_rn(acc[fm][fn][2], acc[fm][fn][3], h1, l1);
            size_t kp = (size_t)(h * 64 + d) >> 1;
            size_t r0 = (size_t)(bb * N_ + n) * KP + kp;
            size_t r1 = (size_t)(bb * N_ + n + 8) * KP + kp;
            g_ctx_h[r0] = h0;  g_ctx_l[r0] = l0;
            g_ctx_h[r1] = h1;  g_ctx_l[r1] = l1;
        }
    }
}

// ============ launcher ========================================================
extern "C" void kernel_launch(void* const* d_in, const int* in_sizes, int n_in,
                              void* d_out, int out_size)
{
    const float* x  = (const float*)d_in[0];
    const float* Wq = (const float*)d_in[1];
    const float* bq = (const float*)d_in[2];
    const float* Wk = (const float*)d_in[3];
    const float* bk = (const float*)d_in[4];
    const float* Wv = (const float*)d_in[5];
    const float* bv = (const float*)d_in[6];
    const float* Wo = (const float*)d_in[7];
    const float* bo = (const float*)d_in[8];

    float* out = (float*)d_out;
    const size_t attn_elems = (size_t)B_ * H_ * N_ * N_;
    float* attn = out + ((size_t)out_size - attn_elems);

    float *q, *k, *v;
    cudaGetSymbolAddress((void**)&q, g_q);
    cudaGetSymbolAddress((void**)&k, g_k);
    cudaGetSymbolAddress((void**)&v, g_v);

    dim3 blk(256);

    convert_x_kernel<<<4096, blk>>>(x);
    convert_w_kernel<<<dim3(16, 16, 4), blk>>>(Wq, Wk, Wv, Wo);
    qkv2_kernel<<<dim3(8, 32, 3), blk>>>(bq, bk, bv, q, k, v);
    scores_kernel<<<dim3(8, 8, BH), blk>>>(q, k, attn);
    entmax_kernel<<<dim3(ROWS / 8), blk>>>(attn);
    attnv_kernel<<<dim3(1, 8, BH), blk>>>(attn, v);
    proj2_kernel<<<dim3(8, 32), blk>>>(bo, out);
}

// round 14
// speedup vs baseline: 1.4752x; 1.0349x over previous
#include <cuda_runtime.h>
#include <math.h>
#include <stdint.h>

#define B_  4
#define N_  1024
#define C_  1024
#define H_  16
#define DH  64
#define BH  (B_*H_)
#define ROWS (BH*N_)
#define KP  512            // kpairs per 1024-length row
#define KPD 32             // kpairs per Dh=64 row

// ---------------- scratch -----------------------------------------------------
__device__ float g_v[(size_t)B_*H_*N_*DH];
// pre-split bf16 kpair arrays
__device__ uint32_t g_x_h[(size_t)4096*KP],  g_x_l[(size_t)4096*KP];
__device__ uint32_t g_wt_h[4][(size_t)1024*KP], g_wt_l[4][(size_t)1024*KP];
__device__ uint32_t g_ctx_h[(size_t)4096*KP], g_ctx_l[(size_t)4096*KP];
// pre-split q/k: [z=b*H+h][n][kpair over Dh]
__device__ uint32_t g_qp_h[(size_t)BH*N_*KPD], g_qp_l[(size_t)BH*N_*KPD];
__device__ uint32_t g_kp_h[(size_t)BH*N_*KPD], g_kp_l[(size_t)BH*N_*KPD];

// ---------------- bf16 3-pass helpers -----------------------------------------
__device__ __forceinline__ void split_pair_rn(float ve, float vo,
                                              uint32_t& hi, uint32_t& lo) {
    asm("cvt.rn.bf16x2.f32 %0, %1, %2;" : "=r"(hi) : "f"(vo), "f"(ve));
    float he  = __uint_as_float(hi << 16);
    float ho  = __uint_as_float(hi & 0xFFFF0000u);
    float le  = ve - he;
    float lof = vo - ho;
    asm("cvt.rn.bf16x2.f32 %0, %1, %2;" : "=r"(lo) : "f"(lof), "f"(le));
}
__device__ __forceinline__ void mma16(float c[4],
                                      uint32_t a0, uint32_t a1, uint32_t a2, uint32_t a3,
                                      uint32_t b0, uint32_t b1) {
    asm("mma.sync.aligned.m16n8k16.row.col.f32.bf16.bf16.f32 "
        "{%0,%1,%2,%3},{%4,%5,%6,%7},{%8,%9},{%0,%1,%2,%3};"
        : "+f"(c[0]), "+f"(c[1]), "+f"(c[2]), "+f"(c[3])
        : "r"(a0), "r"(a1), "r"(a2), "r"(a3), "r"(b0), "r"(b1));
}

// ============ one-time converts ===============================================
__global__ void convert_x_kernel(const float* __restrict__ x)
{
    size_t i = (size_t)blockIdx.x * 256 + threadIdx.x;
    float4 v = ((const float4*)x)[i];
    uint32_t h0, l0, h1, l1;
    split_pair_rn(v.x, v.y, h0, l0);
    split_pair_rn(v.z, v.w, h1, l1);
    ((uint2*)g_x_h)[i] = make_uint2(h0, h1);
    ((uint2*)g_x_l)[i] = make_uint2(l0, l1);
}

__global__ void convert_w_kernel(const float* __restrict__ W0,
                                 const float* __restrict__ W1,
                                 const float* __restrict__ W2,
                                 const float* __restrict__ W3)
{
    __shared__ __align__(16) float s[64][68];   // stride 272B, 16-divisible
    const float* W = (blockIdx.z == 0) ? W0 : (blockIdx.z == 1) ? W1
                   : (blockIdx.z == 2) ? W2 : W3;
    uint32_t* outH = g_wt_h[blockIdx.z];
    uint32_t* outL = g_wt_l[blockIdx.z];
    int t = threadIdx.x;
    int k0 = blockIdx.x * 64, n0 = blockIdx.y * 64;

    #pragma unroll
    for (int i = 0; i < 4; i++) {
        int k = (t >> 4) + i * 16, n4 = (t & 15) * 4;
        *(float4*)&s[k][n4] = *(const float4*)&W[(size_t)(k0 + k) * C_ + n0 + n4];
    }
    __syncthreads();

    #pragma unroll
    for (int j = 0; j < 2; j++) {
        int idx = t + j * 256;
        int nn = idx >> 3, qd = idx & 7;
        uint4 h4, l4;
        uint32_t* hp = (uint32_t*)&h4;
        uint32_t* lp = (uint32_t*)&l4;
        #pragma unroll
        for (int e = 0; e < 4; e++) {
            int kpl = 4 * qd + e;
            split_pair_rn(s[2 * kpl][nn], s[2 * kpl + 1][nn], hp[e], lp[e]);
        }
        size_t off = (size_t)(n0 + nn) * KP + (k0 >> 1) + 4 * qd;
        *(uint4*)&outH[off] = h4;
        *(uint4*)&outL[off] = l4;
    }
}

// ============ GEMM v2: pre-split bf16 operands, 128x128, BK=32 ================
// mode 0: plain fp32 C+bias; mode 1: head fp32 ([B,H,N,Dh]); mode 2: head split
__device__ __forceinline__ void gemm2_body(const uint32_t* __restrict__ AgH,
                                           const uint32_t* __restrict__ AgL,
                                           const uint32_t* __restrict__ WgH,
                                           const uint32_t* __restrict__ WgL,
                                           const float* __restrict__ bias,
                                           float* __restrict__ C,
                                           uint32_t* __restrict__ outH,
                                           uint32_t* __restrict__ outL,
                                           int mode)
{
    __shared__ __align__(16) uint32_t Ah[128][20], Al[128][20];
    __shared__ __align__(16) uint32_t Wh[128][20], Wl[128][20];

    int tid = threadIdx.x;
    int lane = tid & 31, wid = tid >> 5;
    int g = lane >> 2, qq = lane & 3;
    int wm = wid >> 2, wn = wid & 3;
    int row0 = blockIdx.y * 128;
    int col0 = blockIdx.x * 128;

    int fr = tid >> 1, fq = (tid & 1) * 8;

    float acc[4][4][4] = {};

    for (int kb = 0; kb < 32; kb++) {
        size_t abase = (size_t)(row0 + fr) * KP + kb * 16 + fq;
        size_t wbase = (size_t)(col0 + fr) * KP + kb * 16 + fq;
        *(uint4*)&Ah[fr][fq]     = *(const uint4*)&AgH[abase];
        *(uint4*)&Ah[fr][fq + 4] = *(const uint4*)&AgH[abase + 4];
        *(uint4*)&Al[fr][fq]     = *(const uint4*)&AgL[abase];
        *(uint4*)&Al[fr][fq + 4] = *(const uint4*)&AgL[abase + 4];
        *(uint4*)&Wh[fr][fq]     = *(const uint4*)&WgH[wbase];
        *(uint4*)&Wh[fr][fq + 4] = *(const uint4*)&WgH[wbase + 4];
        *(uint4*)&Wl[fr][fq]     = *(const uint4*)&WgL[wbase];
        *(uint4*)&Wl[fr][fq + 4] = *(const uint4*)&WgL[wbase + 4];
        __syncthreads();

        #pragma unroll
        for (int s = 0; s < 2; s++) {
            int pb = s * 8;
            uint32_t bh0[4], bh1[4], bl0[4], bl1[4];
            #pragma unroll
            for (int fn = 0; fn < 4; fn++) {
                int col = wn * 32 + fn * 8 + g;
                bh0[fn] = Wh[col][pb + qq];     bh1[fn] = Wh[col][pb + qq + 4];
                bl0[fn] = Wl[col][pb + qq];     bl1[fn] = Wl[col][pb + qq + 4];
            }
            #pragma unroll
            for (int fm = 0; fm < 4; fm++) {
                int m = wm * 64 + fm * 16 + g;
                uint32_t ah[4], al[4];
                ah[0] = Ah[m][pb + qq];     ah[1] = Ah[m + 8][pb + qq];
                ah[2] = Ah[m][pb + qq + 4]; ah[3] = Ah[m + 8][pb + qq + 4];
                al[0] = Al[m][pb + qq];     al[1] = Al[m + 8][pb + qq];
                al[2] = Al[m][pb + qq + 4]; al[3] = Al[m + 8][pb + qq + 4];
                #pragma unroll
                for (int fn = 0; fn < 4; fn++)
                    mma16(acc[fm][fn], ah[0], ah[1], ah[2], ah[3], bh0[fn], bh1[fn]);
                #pragma unroll
                for (int fn = 0; fn < 4; fn++)
                    mma16(acc[fm][fn], ah[0], ah[1], ah[2], ah[3], bl0[fn], bl1[fn]);
                #pragma unroll
                for (int fn = 0; fn < 4; fn++)
                    mma16(acc[fm][fn], al[0], al[1], al[2], al[3], bh0[fn], bh1[fn]);
            }
        }
        __syncthreads();
    }

    #pragma unroll
    for (int fm = 0; fm < 4; fm++) {
        int rowA = row0 + wm * 64 + fm * 16 + g;
        #pragma unroll
        for (int fn = 0; fn < 4; fn++) {
            int col = col0 + wn * 32 + fn * 8 + 2 * qq;
            float2 p0, p1;
            p0.x = acc[fm][fn][0] + bias[col];
            p0.y = acc[fm][fn][1] + bias[col + 1];
            p1.x = acc[fm][fn][2] + bias[col];
            p1.y = acc[fm][fn][3] + bias[col + 1];
            if (mode == 0) {
                *(float2*)&C[(size_t)rowA * C_ + col] = p0;
                *(float2*)&C[(size_t)(rowA + 8) * C_ + col] = p1;
            } else {
                int h = col >> 6, d = col & 63;
                int bb0 = rowA >> 10, n0 = rowA & 1023;
                int bb1 = (rowA + 8) >> 10, n1 = (rowA + 8) & 1023;
                if (mode == 1) {
                    *(float2*)&C[(((size_t)bb0 * H_ + h) * N_ + n0) * DH + d] = p0;
                    *(float2*)&C[(((size_t)bb1 * H_ + h) * N_ + n1) * DH + d] = p1;
                } else {
                    uint32_t hh, ll;
                    split_pair_rn(p0.x, p0.y, hh, ll);
                    size_t o0 = (((size_t)bb0 * H_ + h) * N_ + n0) * KPD + (d >> 1);
                    outH[o0] = hh; outL[o0] = ll;
                    split_pair_rn(p1.x, p1.y, hh, ll);
                    size_t o1 = (((size_t)bb1 * H_ + h) * N_ + n1) * KPD + (d >> 1);
                    outH[o1] = hh; outL[o1] = ll;
                }
            }
        }
    }
}

__global__ void __launch_bounds__(256, 2)
qkv2_kernel(const float* __restrict__ bq, const float* __restrict__ bk,
            const float* __restrict__ bv, float* __restrict__ v)
{
    int z = blockIdx.z;
    if (z == 0)
        gemm2_body(g_x_h, g_x_l, g_wt_h[0], g_wt_l[0], bq, nullptr, g_qp_h, g_qp_l, 2);
    else if (z == 1)
        gemm2_body(g_x_h, g_x_l, g_wt_h[1], g_wt_l[1], bk, nullptr, g_kp_h, g_kp_l, 2);
    else
        gemm2_body(g_x_h, g_x_l, g_wt_h[2], g_wt_l[2], bv, v, nullptr, nullptr, 1);
}

__global__ void __launch_bounds__(256, 2)
proj2_kernel(const float* __restrict__ bo, float* __restrict__ out)
{
    gemm2_body(g_ctx_h, g_ctx_l, g_wt_h[3], g_wt_l[3], bo, out, nullptr, nullptr, 0);
}

// ============ scores v2: pre-split q/k, per (b,h), S = Q @ K^T * 0.125 ========
__global__ void __launch_bounds__(256, 2)
scores2_kernel(float* __restrict__ S)
{
    __shared__ __align__(16) uint32_t Qh[128][20], Ql[128][20];
    __shared__ __align__(16) uint32_t Kh[128][20], Kl[128][20];

    int z = blockIdx.z;
    const uint32_t* QH = g_qp_h + (size_t)z * N_ * KPD;
    const uint32_t* QL = g_qp_l + (size_t)z * N_ * KPD;
    const uint32_t* KH = g_kp_h + (size_t)z * N_ * KPD;
    const uint32_t* KL = g_kp_l + (size_t)z * N_ * KPD;

    int tid = threadIdx.x;
    int lane = tid & 31, wid = tid >> 5;
    int g = lane >> 2, qq = lane & 3;
    int wm = wid >> 2, wn = wid & 3;
    int row0 = blockIdx.y * 128;
    int col0 = blockIdx.x * 128;

    int fr = tid >> 1, fq = (tid & 1) * 8;

    float acc[4][4][4] = {};

    #pragma unroll
    for (int kb = 0; kb < 2; kb++) {       // 2 blocks of 16 kpairs (Dh=64)
        size_t qbase = (size_t)(row0 + fr) * KPD + kb * 16 + fq;
        size_t kbase = (size_t)(col0 + fr) * KPD + kb * 16 + fq;
        *(uint4*)&Qh[fr][fq] = *(const uint4*)&QH[qbase];
        *(uint4*)&Qh[fr][fq + 4] = *(const uint4*)&QH[qbase + 4];
        *(uint4*)&Ql[fr][fq] = *(const uint4*)&QL[qbase];
        *(uint4*)&Ql[fr][fq + 4] = *(const uint4*)&QL[qbase + 4];
        *(uint4*)&Kh[fr][fq] = *(const uint4*)&KH[kbase];
        *(uint4*)&Kh[fr][fq + 4] = *(const uint4*)&KH[kbase + 4];
        *(uint4*)&Kl[fr][fq] = *(const uint4*)&KL[kbase];
        *(uint4*)&Kl[fr][fq + 4] = *(const uint4*)&KL[kbase + 4];
        __syncthreads();

        #pragma unroll
        for (int s = 0; s < 2; s++) {
            int pb = s * 8;
            uint32_t bh0[4], bh1[4], bl0[4], bl1[4];
            #pragma unroll
            for (int fn = 0; fn < 4; fn++) {
                int col = wn * 32 + fn * 8 + g;
                bh0[fn] = Kh[col][pb + qq];     bh1[fn] = Kh[col][pb + qq + 4];
                bl0[fn] = Kl[col][pb + qq];     bl1[fn] = Kl[col][pb + qq + 4];
            }
            #pragma unroll
            for (int fm = 0; fm < 4; fm++) {
                int m = wm * 64 + fm * 16 + g;
                uint32_t ah[4], al[4];
                ah[0] = Qh[m][pb + qq];     ah[1] = Qh[m + 8][pb + qq];
                ah[2] = Qh[m][pb + qq + 4]; ah[3] = Qh[m + 8][pb + qq + 4];
                al[0] = Ql[m][pb + qq];     al[1] = Ql[m + 8][pb + qq];
                al[2] = Ql[m][pb + qq + 4]; al[3] = Ql[m + 8][pb + qq + 4];
                #pragma unroll
                for (int fn = 0; fn < 4; fn++)
                    mma16(acc[fm][fn], ah[0], ah[1], ah[2], ah[3], bh0[fn], bh1[fn]);
                #pragma unroll
                for (int fn = 0; fn < 4; fn++)
                    mma16(acc[fm][fn], ah[0], ah[1], ah[2], ah[3], bl0[fn], bl1[fn]);
                #pragma unroll
                for (int fn = 0; fn < 4; fn++)
                    mma16(acc[fm][fn], al[0], al[1], al[2], al[3], bh0[fn], bh1[fn]);
            }
        }
        if (kb == 0) __syncthreads();
    }

    float* Sb = S + (size_t)z * N_ * N_;
    #pragma unroll
    for (int fm = 0; fm < 4; fm++) {
        int rowA = row0 + wm * 64 + fm * 16 + g;
        #pragma unroll
        for (int fn = 0; fn < 4; fn++) {
            int col = col0 + wn * 32 + fn * 8 + 2 * qq;
            float2 p0, p1;
            p0.x = acc[fm][fn][0] * 0.125f;
            p0.y = acc[fm][fn][1] * 0.125f;
            p1.x = acc[fm][fn][2] * 0.125f;
            p1.y = acc[fm][fn][3] * 0.125f;
            *(float2*)&Sb[(size_t)rowA * N_ + col] = p0;
            *(float2*)&Sb[(size_t)(rowA + 8) * N_ + col] = p1;
        }
    }
}

// ============ entmax: 10 bisection iters + exact quadratic finish =============
__global__ void entmax_kernel(float* __restrict__ attn)
{
    int warp = threadIdx.x >> 5;
    int lane = threadIdx.x & 31;
    size_t row = (size_t)blockIdx.x * 8 + warp;
    float* S = attn + row * N_;

    float xa[32];
    float mx = -INFINITY;
    #pragma unroll
    for (int i = 0; i < 32; i++) {
        float v = S[i * 32 + lane] * 0.5f;
        xa[i] = v;
        mx = fmaxf(mx, v);
    }
    #pragma unroll
    for (int o = 16; o; o >>= 1)
        mx = fmaxf(mx, __shfl_xor_sync(0xFFFFFFFFu, mx, o));

    float tau_lo = mx - 1.0f;
    float dm = 1.0f - 0.03125f;

    float f_lo = 0.0f;
    #pragma unroll
    for (int i = 0; i < 32; i++) {
        float t = fmaxf(xa[i] - tau_lo, 0.0f);
        f_lo = fmaf(t, t, f_lo);
    }
    #pragma unroll
    for (int o = 16; o; o >>= 1)
        f_lo += __shfl_xor_sync(0xFFFFFFFFu, f_lo, o);
    f_lo -= 1.0f;

    for (int it = 0; it < 10; it++) {
        dm *= 0.5f;
        float tau_m = tau_lo + dm;
        float f = 0.0f;
        #pragma unroll
        for (int i = 0; i < 32; i++) {
            float t = fmaxf(xa[i] - tau_m, 0.0f);
            f = fmaf(t, t, f);
        }
        #pragma unroll
        for (int o = 16; o; o >>= 1)
            f += __shfl_xor_sync(0xFFFFFFFFu, f, o);
        f -= 1.0f;
        if (f * f_lo >= 0.0f) tau_lo = tau_m;
    }

    int   cnt = 0;
    float S1 = 0.0f, S2 = 0.0f;
    #pragma unroll
    for (int i = 0; i < 32; i++) {
        if (xa[i] > tau_lo) {
            cnt += 1;
            S1 += xa[i];
            S2 = fmaf(xa[i], xa[i], S2);
        }
    }
    #pragma unroll
    for (int o = 16; o; o >>= 1) {
        cnt += __shfl_xor_sync(0xFFFFFFFFu, cnt, o);
        S1  += __shfl_xor_sync(0xFFFFFFFFu, S1, o);
        S2  += __shfl_xor_sync(0xFFFFFFFFu, S2, o);
    }
    float kf = (float)cnt;
    float disc = fmaxf(fmaf(S1, S1, -kf * (S2 - 1.0f)), 0.0f);
    float tau = (S1 - sqrtf(disc)) / kf;
    tau = fminf(fmaxf(tau, tau_lo), tau_lo + dm);

    float p[32];
    float s = 0.0f;
    #pragma unroll
    for (int i = 0; i < 32; i++) {
        float t = fmaxf(xa[i] - tau, 0.0f);
        p[i] = t * t;
        s += p[i];
    }
    #pragma unroll
    for (int o = 16; o; o >>= 1)
        s += __shfl_xor_sync(0xFFFFFFFFu, s, o);
    float inv = 1.0f / s;

    #pragma unroll
    for (int i = 0; i < 32; i++)
        S[i * 32 + lane] = p[i] * inv;
}

// ============ ctx = attn @ V per (b,h): 3x bf16 k16 ===========================
// epilogue writes ctx as pre-split bf16 kpairs for proj2.
__global__ void __launch_bounds__(256, 2)
attnv_kernel(const float* __restrict__ Attn, const float* __restrict__ V)
{
    __shared__ uint32_t Ahs[128][12], Als[128][12];
    __shared__ uint32_t Vhs[64][12],  Vls[64][12];

    int z = blockIdx.z;
    int bb = z >> 4, h = z & 15;
    const float* Ab = Attn + (size_t)z * N_ * N_;
    const float* Vb = V    + (size_t)z * N_ * DH;

    int tid = threadIdx.x;
    int lane = tid & 31, wid = tid >> 5;
    int g = lane >> 2, qq = lane & 3;
    int wm = wid >> 1, wn = wid & 1;
    int row0 = blockIdx.y * 128;

    int ar = tid >> 2, ac = (tid & 3) * 4, c2 = (tid & 3) * 2;
    int rp = (tid & 127) >> 4, vc = (tid & 15) * 4;
    bool vload = tid < 128;

    float acc[2][4][4] = {};
    float4 pa[2], pv0, pv1;

    #pragma unroll
    for (int i = 0; i < 2; i++)
        pa[i] = *(const float4*)&Ab[(size_t)(row0 + ar + i * 64) * N_ + ac];
    if (vload) {
        pv0 = *(const float4*)&Vb[(size_t)(2 * rp) * DH + vc];
        pv1 = *(const float4*)&Vb[(size_t)(2 * rp + 1) * DH + vc];
    }

    const int NB = N_ / 16;
    for (int kb = 0; kb < NB; kb++) {
        #pragma unroll
        for (int i = 0; i < 2; i++) {
            uint32_t h0, l0, h1, l1;
            split_pair_rn(pa[i].x, pa[i].y, h0, l0);
            split_pair_rn(pa[i].z, pa[i].w, h1, l1);
            int r = ar + i * 64;
            Ahs[r][c2] = h0; Ahs[r][c2 + 1] = h1;
            Als[r][c2] = l0; Als[r][c2 + 1] = l1;
        }
        if (vload) {
            const float* e = (const float*)&pv0;
            const float* o = (const float*)&pv1;
            #pragma unroll
            for (int j = 0; j < 4; j++) {
                uint32_t hh, ll;
                split_pair_rn(e[j], o[j], hh, ll);
                Vhs[vc + j][rp] = hh;
                Vls[vc + j][rp] = ll;
            }
        }
        __syncthreads();

        if (kb + 1 < NB) {
            int k0 = (kb + 1) * 16;
            #pragma unroll
            for (int i = 0; i < 2; i++)
                pa[i] = *(const float4*)&Ab[(size_t)(row0 + ar + i * 64) * N_ + k0 + ac];
            if (vload) {
                pv0 = *(const float4*)&Vb[(size_t)(k0 + 2 * rp) * DH + vc];
                pv1 = *(const float4*)&Vb[(size_t)(k0 + 2 * rp + 1) * DH + vc];
            }
        }

        uint32_t bh0[4], bh1[4], bl0[4], bl1[4];
        #pragma unroll
        for (int fn = 0; fn < 4; fn++) {
            int col = wn * 32 + fn * 8 + g;
            bh0[fn] = Vhs[col][qq];     bh1[fn] = Vhs[col][qq + 4];
            bl0[fn] = Vls[col][qq];     bl1[fn] = Vls[col][qq + 4];
        }
        #pragma unroll
        for (int fm = 0; fm < 2; fm++) {
            int m = wm * 32 + fm * 16 + g;
            uint32_t ah[4], al[4];
            ah[0] = Ahs[m][qq];     ah[1] = Ahs[m + 8][qq];
            ah[2] = Ahs[m][qq + 4]; ah[3] = Ahs[m + 8][qq + 4];
            al[0] = Als[m][qq];     al[1] = Als[m + 8][qq];
            al[2] = Als[m][qq + 4]; al[3] = Als[m + 8][qq + 4];
            #pragma unroll
            for (int fn = 0; fn < 4; fn++)
                mma16(acc[fm][fn], ah[0], ah[1], ah[2], ah[3], bh0[fn], bh1[fn]);
            #pragma unroll
            for (int fn = 0; fn < 4; fn++)
                mma16(acc[fm][fn], ah[0], ah[1], ah[2], ah[3], bl0[fn], bl1[fn]);
            #pragma unroll
            for (int fn = 0; fn < 4; fn++)
                mma16(acc[fm][fn], al[0], al[1], al[2], al[3], bh0[fn], bh1[fn]);
        }
        __syncthreads();
    }

    // epilogue: split ctx to bf16 kpairs for proj2
    #pragma unroll
    for (int fm = 0; fm < 2; fm++) {
        int n = row0 + wm * 32 + fm * 16 + g;
        #pragma unroll
        for (int fn = 0; fn < 4; fn++) {
            int d = wn * 32 + fn * 8 + 2 * qq;
            uint32_t h0, l0, h1, l1;
            split_pair_rn(acc[fm][fn][0], acc[fm][fn][1], h0, l0);
            split_pair_rn(acc[fm][fn][2], acc[fm][fn][3], h1, l1);
            size_t kp = (size_t)(h * 64 + d) >> 1;
            size_t r0 = (size_t)(bb * N_ + n) * KP + kp;
            size_t r1 = (size_t)(bb * N_ + n + 8) * KP + kp;
            g_ctx_h[r0] = h0;  g_ctx_l[r0] = l0;
            g_ctx_h[r1] = h1;  g_ctx_l[r1] = l1;
        }
    }
}

// ============ launcher ========================================================
extern "C" void kernel_launch(void* const* d_in, const int* in_sizes, int n_in,
                              void* d_out, int out_size)
{
    const float* x  = (const float*)d_in[0];
    const float* Wq = (const float*)d_in[1];
    const float* bq = (const float*)d_in[2];
    const float* Wk = (const float*)d_in[3];
    const float* bk = (const float*)d_in[4];
    const float* Wv = (const float*)d_in[5];
    const float* bv = (const float*)d_in[6];
    const float* Wo = (const float*)d_in[7];
    const float* bo = (const float*)d_in[8];

    float* out = (float*)d_out;
    const size_t attn_elems = (size_t)B_ * H_ * N_ * N_;
    float* attn = out + ((size_t)out_size - attn_elems);

    float* v;
    cudaGetSymbolAddress((void**)&v, g_v);

    dim3 blk(256);

    convert_x_kernel<<<4096, blk>>>(x);
    convert_w_kernel<<<dim3(16, 16, 4), blk>>>(Wq, Wk, Wv, Wo);
    qkv2_kernel<<<dim3(8, 32, 3), blk>>>(bq, bk, bv, v);
    scores2_kernel<<<dim3(8, 8, BH), blk>>>(attn);
    entmax_kernel<<<dim3(ROWS / 8), blk>>>(attn);
    attnv_kernel<<<dim3(1, 8, BH), blk>>>(attn, v);
    proj2_kernel<<<dim3(8, 32), blk>>>(bo, out);
}